// round 10
// baseline (speedup 1.0000x reference)
#include <cuda_runtime.h>

#define NTOK   131072          // H*W*D
#define CCH    96
#define BB     2
#define TN     128             // tokens per tile
#define NTILE  1024            // NTOK/TN
#define NBLK   (BB*NTILE)      // 2048
#define NPART  1248            // 8*144 KV + 96 sumK
#define NCHUNK 8               // token chunks per tile for partials
#define NSEG   32              // reduction segments per batch
#define GRID   148             // persistent blocks
#define RS     132             // smem tile row stride (floats)
#define R4S    (RS/4)
#define WS     100             // weight row stride

__device__ float g_partial[(size_t)NBLK * NCHUNK * NPART];
__device__ float g_red1[NSEG * BB * NPART];
__device__ float g_red[BB * NPART];
__device__ float g_ctx[BB * 1152];

typedef unsigned long long ull;

__device__ __forceinline__ ull pack2(float x, float y) {
    ull r; asm("mov.b64 %0, {%1, %2};" : "=l"(r) : "f"(x), "f"(y)); return r;
}
__device__ __forceinline__ void fma2(ull& d, ull a, ull b) {
    asm("fma.rn.f32x2 %0, %1, %2, %0;" : "+l"(d) : "l"(a), "l"(b));
}
__device__ __forceinline__ float2 unpack2(ull a) {
    float lo, hi; asm("mov.b64 {%0, %1}, %2;" : "=f"(lo), "=f"(hi) : "l"(a));
    return make_float2(lo, hi);
}

// =====================================================================
// Kernel A (persistent, 1024 thr): per tile: stage x -> fused k+v GEMM
// (1 tok x 12 ch, 12 accs) -> exp(k)/v -> fine KV/sumK partials.
// tg = tid&127 (token), og = tid>>7 (head).
// =====================================================================
__global__ void __launch_bounds__(1024, 1)
kv_kernel(const float* __restrict__ x,
          const float* __restrict__ Wk, const float* __restrict__ Wv)
{
    extern __shared__ float sm[];
    float* sX  = sm;                    // [96][RS]
    float* sK  = sX + 96 * RS;          // [96][RS]
    float* sV  = sK + 96 * RS;          // [96][RS]
    float* sWk = sV + 96 * RS;          // [96][WS]
    float* sWv = sWk + 96 * WS;         // [96][WS]

    const int tid = threadIdx.x;
    const int tg  = tid & 127;
    const int og  = tid >> 7;

    for (int i = tid; i < CCH * CCH; i += 1024) {
        int o = i / 96, c = i - o * 96;
        sWk[c * WS + o] = Wk[i];
        sWv[c * WS + o] = Wv[i];
    }

    for (int tile = blockIdx.x; tile < NBLK; tile += GRID) {
        const int b  = tile >> 10;
        const int n0 = (tile & (NTILE - 1)) * TN;

        // stage x tile (float4 coalesced; 3 per thread)
        const float* xb = x + (size_t)b * CCH * NTOK + n0;
        for (int i = tid; i < CCH * (TN / 4); i += 1024) {
            int c = i >> 5, n4 = i & 31;
            ((float4*)(sX + c * RS))[n4] =
                ((const float4*)(xb + (size_t)c * NTOK))[n4];
        }
        __syncthreads();   // sX ready; prev-tile partial reads done

        // fused k+v GEMM: acc j covers channels og*12 + (j>>1)*4 + (j&1)*2 (+1)
        ull ak[6], av[6];
        #pragma unroll
        for (int j = 0; j < 6; j++) { ak[j] = 0ull; av[j] = 0ull; }
        const float* xc = sX + tg;
        #pragma unroll 4
        for (int c = 0; c < 96; c++) {
            float xv = xc[c * RS];
            ull xp = pack2(xv, xv);
            const ulonglong2* wk4 = (const ulonglong2*)(sWk + c * WS + og * 12);
            const ulonglong2* wv4 = (const ulonglong2*)(sWv + c * WS + og * 12);
            #pragma unroll
            for (int jj = 0; jj < 3; jj++) {
                ulonglong2 wk = wk4[jj], wv = wv4[jj];
                fma2(ak[jj * 2 + 0], wk.x, xp);
                fma2(ak[jj * 2 + 1], wk.y, xp);
                fma2(av[jj * 2 + 0], wv.x, xp);
                fma2(av[jj * 2 + 1], wv.y, xp);
            }
        }
        #pragma unroll
        for (int j = 0; j < 6; j++) {
            int o = og * 12 + (j >> 1) * 4 + (j & 1) * 2;
            float2 kk = unpack2(ak[j]);
            float2 vv = unpack2(av[j]);
            sK[o * RS + tg]       = __expf(kk.x);
            sK[(o + 1) * RS + tg] = __expf(kk.y);
            sV[o * RS + tg]       = vv.x;
            sV[(o + 1) * RS + tg] = vv.y;
        }
        __syncthreads();   // sK/sV complete

        // fine partials: 576 KV tasks (4x4 ch-block x 16-tok chunk)
        // + 192 sumK tasks (4 ch x 16-tok chunk). Warp-aligned split.
        if (tid < 576) {
            int chunk = tid & 7, bidx = tid >> 3;        // bidx 0..71
            int h = bidx / 9, r = bidx - h * 9, db = r / 3, eb = r - db * 3;
            const float4* pk0 = (const float4*)(sK + (h * 12 + db * 4) * RS) + chunk * 4;
            const float4* pv0 = (const float4*)(sV + (h * 12 + eb * 4) * RS) + chunk * 4;
            ull a2[16];
            #pragma unroll
            for (int i = 0; i < 16; i++) a2[i] = 0ull;
            #pragma unroll
            for (int t = 0; t < 4; t++) {
                float4 K[4], V[4];
                #pragma unroll
                for (int i = 0; i < 4; i++) { K[i] = pk0[i * R4S + t]; V[i] = pv0[i * R4S + t]; }
                ull Kxy[4], Kzw[4], Vxy[4], Vzw[4];
                #pragma unroll
                for (int i = 0; i < 4; i++) {
                    Kxy[i] = pack2(K[i].x, K[i].y); Kzw[i] = pack2(K[i].z, K[i].w);
                    Vxy[i] = pack2(V[i].x, V[i].y); Vzw[i] = pack2(V[i].z, V[i].w);
                }
                #pragma unroll
                for (int i = 0; i < 4; i++)
                    #pragma unroll
                    for (int j = 0; j < 4; j++) {
                        fma2(a2[i * 4 + j], Kxy[i], Vxy[j]);
                        fma2(a2[i * 4 + j], Kzw[i], Vzw[j]);
                    }
            }
            float* po = g_partial + ((size_t)tile * NCHUNK + chunk) * NPART;
            #pragma unroll
            for (int i = 0; i < 4; i++)
                #pragma unroll
                for (int j = 0; j < 4; j++) {
                    float2 v = unpack2(a2[i * 4 + j]);
                    po[h * 144 + (db * 4 + i) * 12 + eb * 4 + j] = v.x + v.y;
                }
        } else if (tid < 768) {
            int s = tid - 576;
            int chunk = s & 7, ci = s >> 3;              // ci 0..23
            float a[4] = {0.f, 0.f, 0.f, 0.f};
            #pragma unroll
            for (int t = 0; t < 4; t++)
                #pragma unroll
                for (int i = 0; i < 4; i++) {
                    float4 K = ((const float4*)(sK + (ci * 4 + i) * RS))[chunk * 4 + t];
                    a[i] += K.x + K.y + K.z + K.w;
                }
            float* po = g_partial + ((size_t)tile * NCHUNK + chunk) * NPART;
            #pragma unroll
            for (int i = 0; i < 4; i++) po[1152 + ci * 4 + i] = a[i];
        }
        // next-loop barrier orders partial reads vs sK/sV rewrite
    }
}

// ===== stage-1 reduce: 32 segments of 256 chunk-rows each =====
__global__ void red1_kernel()
{
    int idx = blockIdx.x * 256 + threadIdx.x;
    int b = blockIdx.y, seg = blockIdx.z;
    if (idx >= NPART) return;
    float a = 0.f;
    const float* p = g_partial +
        ((size_t)b * NTILE * NCHUNK + (size_t)seg * (NTILE * NCHUNK / NSEG)) * NPART + idx;
    #pragma unroll 8
    for (int t = 0; t < NTILE * NCHUNK / NSEG; t++) a += p[(size_t)t * NPART];
    g_red1[(seg * BB + b) * NPART + idx] = a;
}

// ===== stage-2 reduce (fixed order) =====
__global__ void red2_kernel()
{
    int gid = blockIdx.x * 256 + threadIdx.x;
    if (gid >= BB * NPART) return;
    int b = gid / NPART, idx = gid - b * NPART;
    float a = 0.f;
    #pragma unroll
    for (int s = 0; s < NSEG; s++) a += g_red1[(s * BB + b) * NPART + idx];
    g_red[gid] = a;
}

// ===== context[b,h,d,e] = KV[h,d,e] / sumK[h*12+d] =====
__global__ void ctx_kernel()
{
    int gid = blockIdx.x * 256 + threadIdx.x;
    if (gid >= BB * 1152) return;
    int b = gid / 1152;
    int r = gid - b * 1152;
    int h = r / 144, d = (r % 144) / 12;
    g_ctx[gid] = g_red[b * NPART + r] / g_red[b * NPART + 1152 + h * 12 + d];
}

// =====================================================================
// Kernel C (persistent, 1024 thr): stage x -> q GEMM -> softmax+attn
// in-place -> proj GEMM -> out. 1 token x 12 ch per thread.
// =====================================================================
__global__ void __launch_bounds__(1024, 1)
out2_kernel(const float* __restrict__ x, const float* __restrict__ Wq,
            const float* __restrict__ Wproj, float* __restrict__ out)
{
    extern __shared__ float sm[];
    float* sX   = sm;                   // [96][RS]: x, then attn in-place
    float* sWq  = sX + 96 * RS;         // [96][WS]
    float* sWp  = sWq + 96 * WS;        // [96][WS]
    float* sCtx = sWp + 96 * WS;        // BB*1152

    const int tid = threadIdx.x;
    const int tg  = tid & 127;
    const int og  = tid >> 7;

    for (int i = tid; i < CCH * CCH; i += 1024) {
        int o = i / 96, c = i - o * 96;
        sWq[c * WS + o] = Wq[i];
        sWp[c * WS + o] = Wproj[i];
    }
    for (int i = tid; i < BB * 1152; i += 1024) sCtx[i] = g_ctx[i];

    for (int tile = blockIdx.x; tile < NBLK; tile += GRID) {
        const int b  = tile >> 10;
        const int n0 = (tile & (NTILE - 1)) * TN;

        const float* xb = x + (size_t)b * CCH * NTOK + n0;
        for (int i = tid; i < CCH * (TN / 4); i += 1024) {
            int c = i >> 5, n4 = i & 31;
            ((float4*)(sX + c * RS))[n4] =
                ((const float4*)(xb + (size_t)c * NTOK))[n4];
        }
        __syncthreads();   // sX staged (and prev-tile proj reads done)

        // q GEMM (6 accs)
        ull aq[6];
        #pragma unroll
        for (int j = 0; j < 6; j++) aq[j] = 0ull;
        const float* xc = sX + tg;
        #pragma unroll 4
        for (int c = 0; c < 96; c++) {
            float xv = xc[c * RS];
            ull xp = pack2(xv, xv);
            const ulonglong2* w4 = (const ulonglong2*)(sWq + c * WS + og * 12);
            #pragma unroll
            for (int jj = 0; jj < 3; jj++) {
                ulonglong2 w = w4[jj];
                fma2(aq[jj * 2 + 0], w.x, xp);
                fma2(aq[jj * 2 + 1], w.y, xp);
            }
        }
        __syncthreads();   // all reads of x from sX done

        // softmax + attn for this token; write into sX in-place
        {
            float qv[12];
            #pragma unroll
            for (int j = 0; j < 6; j++) {
                float2 v = unpack2(aq[j]);
                int o = (j >> 1) * 4 + (j & 1) * 2;
                qv[o] = v.x; qv[o + 1] = v.y;
            }
            float m = qv[0];
            #pragma unroll
            for (int i = 1; i < 12; i++) m = fmaxf(m, qv[i]);
            float p[12]; float sum = 0.f;
            #pragma unroll
            for (int i = 0; i < 12; i++) { p[i] = __expf(qv[i] - m); sum += p[i]; }
            float inv = 1.f / sum;

            const ull* cx2 = (const ull*)(sCtx + b * 1152 + og * 144);
            ull at[6];
            #pragma unroll
            for (int j = 0; j < 6; j++) at[j] = 0ull;
            #pragma unroll
            for (int d = 0; d < 12; d++) {
                ull pd = pack2(p[d], p[d]);
                #pragma unroll
                for (int j = 0; j < 6; j++) fma2(at[j], cx2[d * 6 + j], pd);
            }
            #pragma unroll
            for (int j = 0; j < 6; j++) {
                float2 v = unpack2(at[j]);
                sX[(og * 12 + 2 * j) * RS + tg]     = v.x * inv;
                sX[(og * 12 + 2 * j + 1) * RS + tg] = v.y * inv;
            }
        }
        __syncthreads();   // attn tile complete

        // proj GEMM (6 accs)
        ull ap[6];
        #pragma unroll
        for (int j = 0; j < 6; j++) ap[j] = 0ull;
        #pragma unroll 4
        for (int c = 0; c < 96; c++) {
            float av = xc[c * RS];
            ull xp = pack2(av, av);
            const ulonglong2* w4 = (const ulonglong2*)(sWp + c * WS + og * 12);
            #pragma unroll
            for (int jj = 0; jj < 3; jj++) {
                ulonglong2 w = w4[jj];
                fma2(ap[jj * 2 + 0], w.x, xp);
                fma2(ap[jj * 2 + 1], w.y, xp);
            }
        }

        float* ob = out + (size_t)b * CCH * NTOK + n0 + tg;
        #pragma unroll
        for (int j = 0; j < 6; j++) {
            float2 v = unpack2(ap[j]);
            int o = og * 12 + (j >> 1) * 4 + (j & 1) * 2;
            ob[(size_t)o * NTOK]       = v.x;
            ob[(size_t)(o + 1) * NTOK] = v.y;
        }
        __syncthreads();   // proj reads of sX done before next staging
    }
}

extern "C" void kernel_launch(void* const* d_in, const int* in_sizes, int n_in,
                              void* d_out, int out_size)
{
    const float* x  = (const float*)d_in[0];
    const float* Wq = (const float*)d_in[1];
    const float* Wk = (const float*)d_in[2];
    const float* Wv = (const float*)d_in[3];
    const float* Wp = (const float*)d_in[4];
    float* out = (float*)d_out;

    const size_t smA = (size_t)(3 * 96 * RS + 2 * 96 * WS) * sizeof(float);        // 228,864 B
    const size_t smC = (size_t)(96 * RS + 2 * 96 * WS + BB * 1152) * sizeof(float);// 136,704 B
    cudaFuncSetAttribute(kv_kernel,   cudaFuncAttributeMaxDynamicSharedMemorySize, (int)smA);
    cudaFuncSetAttribute(out2_kernel, cudaFuncAttributeMaxDynamicSharedMemorySize, (int)smC);

    kv_kernel<<<GRID, 1024, smA>>>(x, Wk, Wv);
    red1_kernel<<<dim3(5, BB, NSEG), 256>>>();
    red2_kernel<<<(BB * NPART + 255) / 256, 256>>>();
    ctx_kernel<<<(BB * 1152 + 255) / 256, 256>>>();
    out2_kernel<<<GRID, 1024, smC>>>(x, Wq, Wp, out);
}

// round 12
// speedup vs baseline: 1.1613x; 1.1613x over previous
#include <cuda_runtime.h>
#include <cstdint>

#define NTOK   131072
#define CCH    96
#define BB     2
#define NPART  1248            // 8*144 KV + 96 sumK
#define NSEG   32

// kv tiling: 64 tokens/tile
#define TNK    64
#define KTPB   2048            // kv tiles per batch (NTOK/64)
#define KBLK   (BB*KTPB)       // 4096
#define NCHUNK 2
#define RSK    68              // kv smem row stride (272B, 16-aligned)
#define R4K    17

// out tiling: 128 tokens/tile
#define TNO    128
#define OTPB   1024
#define OBLK   (BB*OTPB)       // 2048
#define RSO    132             // out smem row stride (528B, 16-aligned)

__device__ float g_partial[(size_t)KBLK * NCHUNK * NPART];  // ~41 MB
__device__ float g_red1[NSEG * BB * NPART];
__device__ float g_red[BB * NPART];
__device__ float g_WkT[9216];          // W^T: [c][o]
__device__ float g_WvT[9216];
__device__ float g_WqT[9216];
__device__ float g_WCt[BB * 9216];     // WC^T: [b][c'][o]

typedef unsigned long long ull;

__device__ __forceinline__ ull pack2(float x, float y) {
    ull r; asm("mov.b64 %0, {%1, %2};" : "=l"(r) : "f"(x), "f"(y)); return r;
}
__device__ __forceinline__ void fma2(ull& d, ull a, ull b) {
    asm("fma.rn.f32x2 %0, %1, %2, %0;" : "+l"(d) : "l"(a), "l"(b));
}
__device__ __forceinline__ float2 unpack2(ull a) {
    float lo, hi; asm("mov.b64 {%0, %1}, %2;" : "=f"(lo), "=f"(hi) : "l"(a));
    return make_float2(lo, hi);
}

// ===== prep: transpose the three input-side weights =====
__global__ void prep_kernel(const float* __restrict__ Wq,
                            const float* __restrict__ Wk,
                            const float* __restrict__ Wv)
{
    int i = blockIdx.x * 256 + threadIdx.x;
    if (i >= 9216) return;
    int o = i / 96, c = i - o * 96;
    g_WqT[c * 96 + o] = Wq[i];
    g_WkT[c * 96 + o] = Wk[i];
    g_WvT[c * 96 + o] = Wv[i];
}

// =====================================================================
// Kernel A: 64-token tile, 256 thr, 2 CTAs/SM. Stage x -> fused k+v
// GEMM (weights via uniform LDG from g_W*T) -> exp(k)/v -> partials.
// tg = tid&31 (2 tokens), og = tid>>5 (head).
// =====================================================================
__global__ void __launch_bounds__(256, 2)
kv_kernel(const float* __restrict__ x)
{
    extern __shared__ float sm[];
    float* sX = sm;                 // [96][RSK]
    float* sK = sX + 96 * RSK;      // [96][RSK]
    float* sV = sK + 96 * RSK;      // [96][RSK]

    const int tile = blockIdx.x;
    const int b    = tile >> 11;
    const int n0   = (tile & (KTPB - 1)) * TNK;
    const int tid  = threadIdx.x;
    const int tg   = tid & 31;
    const int og   = tid >> 5;
    const int nt   = tg * 2;

    // stage x tile (96 x 16 float4)
    const float* xb = x + (size_t)b * CCH * NTOK + n0;
    #pragma unroll
    for (int it = 0; it < 6; it++) {
        int i = tid + it * 256;
        int c = i >> 4, n4 = i & 15;
        ((float4*)(sX + c * RSK))[n4] = ((const float4*)(xb + (size_t)c * NTOK))[n4];
    }
    __syncthreads();

    // fused k+v GEMM: 12+12 accs (2 tok x 12 ch x 2 mats)
    ull ak[12], av[12];
    #pragma unroll
    for (int j = 0; j < 12; j++) { ak[j] = 0ull; av[j] = 0ull; }
    const float* wkb = g_WkT + og * 12;
    const float* wvb = g_WvT + og * 12;
    #pragma unroll 2
    for (int c = 0; c < 96; c++) {
        float2 xv = *(const float2*)(sX + c * RSK + nt);
        ull x0 = pack2(xv.x, xv.x), x1 = pack2(xv.y, xv.y);
        const ulonglong2* wk4 = (const ulonglong2*)(wkb + c * 96);
        const ulonglong2* wv4 = (const ulonglong2*)(wvb + c * 96);
        #pragma unroll
        for (int jj = 0; jj < 3; jj++) {
            ulonglong2 wk = wk4[jj], wv = wv4[jj];
            fma2(ak[jj * 4 + 0], wk.x, x0); fma2(ak[jj * 4 + 1], wk.x, x1);
            fma2(ak[jj * 4 + 2], wk.y, x0); fma2(ak[jj * 4 + 3], wk.y, x1);
            fma2(av[jj * 4 + 0], wv.x, x0); fma2(av[jj * 4 + 1], wv.x, x1);
            fma2(av[jj * 4 + 2], wv.y, x0); fma2(av[jj * 4 + 3], wv.y, x1);
        }
    }

    // write exp(k) -> sK, v -> sV (float2 = 2 tokens)
    #pragma unroll
    for (int jj = 0; jj < 3; jj++)
        #pragma unroll
        for (int s = 0; s < 2; s++) {
            float2 k0 = unpack2(ak[jj * 4 + s * 2 + 0]);   // token nt (ch, ch+1)
            float2 k1 = unpack2(ak[jj * 4 + s * 2 + 1]);   // token nt+1
            float2 v0 = unpack2(av[jj * 4 + s * 2 + 0]);
            float2 v1 = unpack2(av[jj * 4 + s * 2 + 1]);
            int o = og * 12 + jj * 4 + s * 2;
            *(float2*)(sK + o * RSK + nt)       = make_float2(__expf(k0.x), __expf(k1.x));
            *(float2*)(sK + (o + 1) * RSK + nt) = make_float2(__expf(k0.y), __expf(k1.y));
            *(float2*)(sV + o * RSK + nt)       = make_float2(v0.x, v1.x);
            *(float2*)(sV + (o + 1) * RSK + nt) = make_float2(v0.y, v1.y);
        }
    __syncthreads();

    // partials: 144 KV tasks (4x4 ch-block x 32-tok chunk) + 48 sumK
    float* po;
    if (tid < 144) {
        int chunk = tid & 1, bidx = tid >> 1;
        int h = bidx / 9, r = bidx - h * 9, db = r / 3, eb = r - db * 3;
        const float4* pk0 = (const float4*)(sK + (h * 12 + db * 4) * RSK) + chunk * 8;
        const float4* pv0 = (const float4*)(sV + (h * 12 + eb * 4) * RSK) + chunk * 8;
        ull a2[16];
        #pragma unroll
        for (int i = 0; i < 16; i++) a2[i] = 0ull;
        #pragma unroll 2
        for (int t = 0; t < 8; t++) {
            float4 K[4], V[4];
            #pragma unroll
            for (int i = 0; i < 4; i++) { K[i] = pk0[i * R4K + t]; V[i] = pv0[i * R4K + t]; }
            ull Kxy[4], Kzw[4], Vxy[4], Vzw[4];
            #pragma unroll
            for (int i = 0; i < 4; i++) {
                Kxy[i] = pack2(K[i].x, K[i].y); Kzw[i] = pack2(K[i].z, K[i].w);
                Vxy[i] = pack2(V[i].x, V[i].y); Vzw[i] = pack2(V[i].z, V[i].w);
            }
            #pragma unroll
            for (int i = 0; i < 4; i++)
                #pragma unroll
                for (int j = 0; j < 4; j++) {
                    fma2(a2[i * 4 + j], Kxy[i], Vxy[j]);
                    fma2(a2[i * 4 + j], Kzw[i], Vzw[j]);
                }
        }
        po = g_partial + ((size_t)tile * NCHUNK + chunk) * NPART;
        #pragma unroll
        for (int i = 0; i < 4; i++)
            #pragma unroll
            for (int j = 0; j < 4; j++) {
                float2 v = unpack2(a2[i * 4 + j]);
                po[h * 144 + (db * 4 + i) * 12 + eb * 4 + j] = v.x + v.y;
            }
    } else if (tid < 192) {
        int s = tid - 144;
        int chunk = s & 1, ci = s >> 1;    // ci 0..23
        float a[4] = {0.f, 0.f, 0.f, 0.f};
        #pragma unroll 2
        for (int t = 0; t < 8; t++)
            #pragma unroll
            for (int i = 0; i < 4; i++) {
                float4 K = ((const float4*)(sK + (ci * 4 + i) * RSK))[chunk * 8 + t];
                a[i] += K.x + K.y + K.z + K.w;
            }
        po = g_partial + ((size_t)tile * NCHUNK + chunk) * NPART;
        #pragma unroll
        for (int i = 0; i < 4; i++) po[1152 + ci * 4 + i] = a[i];
    }
}

// ===== stage-1 reduce: 32 segments of 128 chunk-rows per batch =====
__global__ void red1_kernel()
{
    int idx = blockIdx.x * 256 + threadIdx.x;
    int b = blockIdx.y, seg = blockIdx.z;
    if (idx >= NPART) return;
    float a = 0.f;
    const float* p = g_partial +
        ((size_t)b * KTPB * NCHUNK + (size_t)seg * (KTPB * NCHUNK / NSEG)) * NPART + idx;
    #pragma unroll 8
    for (int t = 0; t < KTPB * NCHUNK / NSEG; t++) a += p[(size_t)t * NPART];
    g_red1[(seg * BB + b) * NPART + idx] = a;
}

// ===== stage-2 reduce (fixed order) =====
__global__ void red2_kernel()
{
    int gid = blockIdx.x * 256 + threadIdx.x;
    if (gid >= BB * NPART) return;
    int b = gid / NPART, idx = gid - b * NPART;
    float a = 0.f;
    #pragma unroll
    for (int s = 0; s < NSEG; s++) a += g_red1[(s * BB + b) * NPART + idx];
    g_red[gid] = a;
}

// ===== WC^T[b][c'][o] = (sum_e Wproj[o,h12+e] * KV[b,h,d,e]) / sumK[b,c'] =====
__global__ void ctx2_kernel(const float* __restrict__ Wproj)
{
    int gid = blockIdx.x * 256 + threadIdx.x;
    if (gid >= BB * 9216) return;
    int b = gid / 9216;
    int r = gid - b * 9216;
    int o = r / 96, cp = r - o * 96;       // cp = h*12+d
    int h = cp / 12, d = cp - h * 12;
    const float* kv = g_red + b * NPART + h * 144 + d * 12;
    const float* wp = Wproj + o * 96 + h * 12;
    float a = 0.f;
    #pragma unroll
    for (int e = 0; e < 12; e++) a += wp[e] * kv[e];
    g_WCt[(b * 96 + cp) * 96 + o] = a / g_red[b * NPART + 1152 + cp];
}

// =====================================================================
// Kernel C: 128-token tile, 512 thr, 2 CTAs/SM (8 warps/SMSP).
// Stage x -> q GEMM (WqT via LDG) -> softmax -> p in-place -> WC GEMM
// (WCt via LDG) -> out. tg = tid&63 (2 tokens), og = tid>>6.
// =====================================================================
__global__ void __launch_bounds__(512, 2)
out2_kernel(const float* __restrict__ x, float* __restrict__ out)
{
    extern __shared__ float sm[];
    float* sX = sm;                 // [96][RSO]: x, then p in-place

    const int tile = blockIdx.x;
    const int b    = tile >> 10;
    const int n0   = (tile & (OTPB - 1)) * TNO;
    const int tid  = threadIdx.x;
    const int tg   = tid & 63;
    const int og   = tid >> 6;
    const int nt   = tg * 2;

    // stage x (96 x 32 float4)
    const float* xb = x + (size_t)b * CCH * NTOK + n0;
    #pragma unroll
    for (int it = 0; it < 6; it++) {
        int i = tid + it * 512;
        int c = i >> 5, n4 = i & 31;
        ((float4*)(sX + c * RSO))[n4] = ((const float4*)(xb + (size_t)c * NTOK))[n4];
    }
    __syncthreads();

    // q GEMM: 12 accs (2 tok x 12 ch)
    ull aq[12];
    #pragma unroll
    for (int j = 0; j < 12; j++) aq[j] = 0ull;
    const float* wqb = g_WqT + og * 12;
    #pragma unroll 2
    for (int c = 0; c < 96; c++) {
        float2 xv = *(const float2*)(sX + c * RSO + nt);
        ull x0 = pack2(xv.x, xv.x), x1 = pack2(xv.y, xv.y);
        const ulonglong2* w4 = (const ulonglong2*)(wqb + c * 96);
        #pragma unroll
        for (int jj = 0; jj < 3; jj++) {
            ulonglong2 w = w4[jj];
            fma2(aq[jj * 4 + 0], w.x, x0); fma2(aq[jj * 4 + 1], w.x, x1);
            fma2(aq[jj * 4 + 2], w.y, x0); fma2(aq[jj * 4 + 3], w.y, x1);
        }
    }
    __syncthreads();   // all q reads of sX complete

    // softmax over head dim per token; write p into sX in-place
    #pragma unroll
    for (int t = 0; t < 2; t++) {
        float qv[12];
        #pragma unroll
        for (int jj = 0; jj < 3; jj++)
            #pragma unroll
            for (int s = 0; s < 2; s++) {
                float2 v = unpack2(aq[jj * 4 + s * 2 + t]);
                qv[jj * 4 + s * 2]     = v.x;
                qv[jj * 4 + s * 2 + 1] = v.y;
            }
        float m = qv[0];
        #pragma unroll
        for (int i = 1; i < 12; i++) m = fmaxf(m, qv[i]);
        float p[12]; float sum = 0.f;
        #pragma unroll
        for (int i = 0; i < 12; i++) { p[i] = __expf(qv[i] - m); sum += p[i]; }
        float inv = 1.f / sum;
        #pragma unroll
        for (int i = 0; i < 12; i++)
            sX[(og * 12 + i) * RSO + nt + t] = p[i] * inv;
    }
    __syncthreads();   // p tile complete

    // WC GEMM: out[o][n] = sum_c' WC[o][c'] * p[c'][n]
    ull ap[12];
    #pragma unroll
    for (int j = 0; j < 12; j++) ap[j] = 0ull;
    const float* wcb = g_WCt + b * 9216 + og * 12;
    #pragma unroll 2
    for (int c = 0; c < 96; c++) {
        float2 pv = *(const float2*)(sX + c * RSO + nt);
        ull x0 = pack2(pv.x, pv.x), x1 = pack2(pv.y, pv.y);
        const ulonglong2* w4 = (const ulonglong2*)(wcb + c * 96);
        #pragma unroll
        for (int jj = 0; jj < 3; jj++) {
            ulonglong2 w = w4[jj];
            fma2(ap[jj * 4 + 0], w.x, x0); fma2(ap[jj * 4 + 1], w.x, x1);
            fma2(ap[jj * 4 + 2], w.y, x0); fma2(ap[jj * 4 + 3], w.y, x1);
        }
    }

    float* ob = out + (size_t)b * CCH * NTOK + n0 + nt;
    #pragma unroll
    for (int jj = 0; jj < 3; jj++)
        #pragma unroll
        for (int s = 0; s < 2; s++) {
            float2 a0 = unpack2(ap[jj * 4 + s * 2 + 0]);   // token nt (ch, ch+1)
            float2 a1 = unpack2(ap[jj * 4 + s * 2 + 1]);   // token nt+1
            int o = og * 12 + jj * 4 + s * 2;
            *(float2*)(ob + (size_t)o * NTOK)       = make_float2(a0.x, a1.x);
            *(float2*)(ob + (size_t)(o + 1) * NTOK) = make_float2(a0.y, a1.y);
        }
}

extern "C" void kernel_launch(void* const* d_in, const int* in_sizes, int n_in,
                              void* d_out, int out_size)
{
    const float* x  = (const float*)d_in[0];
    const float* Wq = (const float*)d_in[1];
    const float* Wk = (const float*)d_in[2];
    const float* Wv = (const float*)d_in[3];
    const float* Wp = (const float*)d_in[4];
    float* out = (float*)d_out;

    const size_t smA = (size_t)(3 * 96 * RSK) * sizeof(float);   // 78,336 B
    const size_t smC = (size_t)(96 * RSO) * sizeof(float);       // 50,688 B
    cudaFuncSetAttribute(kv_kernel,   cudaFuncAttributeMaxDynamicSharedMemorySize, (int)smA);
    cudaFuncSetAttribute(out2_kernel, cudaFuncAttributeMaxDynamicSharedMemorySize, (int)smC);

    prep_kernel<<<36, 256>>>(Wq, Wk, Wv);
    kv_kernel<<<KBLK, 256, smA>>>(x);
    red1_kernel<<<dim3(5, BB, NSEG), 256>>>();
    red2_kernel<<<(BB * NPART + 255) / 256, 256>>>();
    ctx2_kernel<<<(BB * 9216 + 255) / 256, 256>>>(Wp);
    out2_kernel<<<OBLK, 512, smC>>>(x, out);
}

// round 13
// speedup vs baseline: 1.4082x; 1.2127x over previous
#include <cuda_runtime.h>
#include <cstdint>

#define NTOK   131072
#define CCH    96
#define BB     2
#define TN     128
#define NTILE  1024
#define NBLK   (BB*NTILE)      // 2048
#define NPART  1248
#define NCHUNK 8
#define NSEG   32
#define RS     132
#define R4S    (RS/4)
#define WS     100

__device__ float g_partial[(size_t)NBLK * NCHUNK * NPART];
__device__ float g_red1[NSEG * BB * NPART];
__device__ float g_red[BB * NPART];
__device__ float g_WCt[BB * 9216];     // folded (Wproj @ ctx)^T : [b][c'][o]

typedef unsigned long long ull;

__device__ __forceinline__ ull pack2(float x, float y) {
    ull r; asm("mov.b64 %0, {%1, %2};" : "=l"(r) : "f"(x), "f"(y)); return r;
}
__device__ __forceinline__ void fma2(ull& d, ull a, ull b) {
    asm("fma.rn.f32x2 %0, %1, %2, %0;" : "+l"(d) : "l"(a), "l"(b));
}
__device__ __forceinline__ float2 unpack2(ull a) {
    float lo, hi; asm("mov.b64 {%0, %1}, %2;" : "=f"(lo), "=f"(hi) : "l"(a));
    return make_float2(lo, hi);
}

// =====================================================================
// Kernel A: 1024 thr, matrix-split. mat = tid>>9 (0:k, 1:v),
// og = (tid>>6)&7 (head), tg = tid&63 (2 tokens).
// stage x -> GEMM (12 accs) -> exp(k)/v -> fine partials.
// =====================================================================
__global__ void __launch_bounds__(1024, 1)
kv_kernel(const float* __restrict__ x,
          const float* __restrict__ Wk, const float* __restrict__ Wv)
{
    extern __shared__ float sm[];
    float* sX  = sm;                    // [96][RS]
    float* sK  = sX + 96 * RS;          // [96][RS]
    float* sV  = sK + 96 * RS;          // [96][RS]
    float* sWk = sV + 96 * RS;          // [96][WS]
    float* sWv = sWk + 96 * WS;         // [96][WS]

    const int tile = blockIdx.x;
    const int b    = tile >> 10;
    const int n0   = (tile & (NTILE - 1)) * TN;
    const int tid  = threadIdx.x;
    const int mat  = tid >> 9;
    const int og   = (tid >> 6) & 7;
    const int tg   = tid & 63;
    const int nt   = tg * 2;

    // stage x (3072 float4 over 1024 threads) + weights transposed
    const float* xb = x + (size_t)b * CCH * NTOK + n0;
    #pragma unroll
    for (int it = 0; it < 3; it++) {
        int i = tid + it * 1024;
        int c = i >> 5, n4 = i & 31;
        ((float4*)(sX + c * RS))[n4] = ((const float4*)(xb + (size_t)c * NTOK))[n4];
    }
    for (int i = tid; i < CCH * CCH; i += 1024) {
        int o = i / 96, c = i - o * 96;
        sWk[c * WS + o] = Wk[i];
        sWv[c * WS + o] = Wv[i];
    }
    __syncthreads();

    // GEMM for my matrix: 12 accs (2 tok x 12 ch)
    const float* sW = mat ? sWv : sWk;
    ull acc[12];
    #pragma unroll
    for (int j = 0; j < 12; j++) acc[j] = 0ull;
    #pragma unroll 2
    for (int c = 0; c < 96; c++) {
        float2 xv = *(const float2*)(sX + c * RS + nt);
        ull x0 = pack2(xv.x, xv.x), x1 = pack2(xv.y, xv.y);
        const ulonglong2* w4 = (const ulonglong2*)(sW + c * WS + og * 12);
        #pragma unroll
        for (int jj = 0; jj < 3; jj++) {
            ulonglong2 w = w4[jj];
            fma2(acc[jj * 4 + 0], w.x, x0); fma2(acc[jj * 4 + 1], w.x, x1);
            fma2(acc[jj * 4 + 2], w.y, x0); fma2(acc[jj * 4 + 3], w.y, x1);
        }
    }

    // write results: k threads -> exp into sK; v threads -> sV
    float* dst = mat ? sV : sK;
    #pragma unroll
    for (int jj = 0; jj < 3; jj++)
        #pragma unroll
        for (int s = 0; s < 2; s++) {
            float2 a0 = unpack2(acc[jj * 4 + s * 2 + 0]);   // token nt
            float2 a1 = unpack2(acc[jj * 4 + s * 2 + 1]);   // token nt+1
            int o = og * 12 + jj * 4 + s * 2;
            if (mat == 0) {
                *(float2*)(dst + o * RS + nt)       = make_float2(__expf(a0.x), __expf(a1.x));
                *(float2*)(dst + (o + 1) * RS + nt) = make_float2(__expf(a0.y), __expf(a1.y));
            } else {
                *(float2*)(dst + o * RS + nt)       = make_float2(a0.x, a1.x);
                *(float2*)(dst + (o + 1) * RS + nt) = make_float2(a0.y, a1.y);
            }
        }
    __syncthreads();

    // fine partials: 576 KV tasks (4x4 ch x 16-tok chunk) + 192 sumK
    if (tid < 576) {
        int chunk = tid & 7, bidx = tid >> 3;        // bidx 0..71
        int h = bidx / 9, r = bidx - h * 9, db = r / 3, eb = r - db * 3;
        const float4* pk0 = (const float4*)(sK + (h * 12 + db * 4) * RS) + chunk * 4;
        const float4* pv0 = (const float4*)(sV + (h * 12 + eb * 4) * RS) + chunk * 4;
        ull a2[16];
        #pragma unroll
        for (int i = 0; i < 16; i++) a2[i] = 0ull;
        #pragma unroll
        for (int t = 0; t < 4; t++) {
            float4 K[4], V[4];
            #pragma unroll
            for (int i = 0; i < 4; i++) { K[i] = pk0[i * R4S + t]; V[i] = pv0[i * R4S + t]; }
            ull Kxy[4], Kzw[4], Vxy[4], Vzw[4];
            #pragma unroll
            for (int i = 0; i < 4; i++) {
                Kxy[i] = pack2(K[i].x, K[i].y); Kzw[i] = pack2(K[i].z, K[i].w);
                Vxy[i] = pack2(V[i].x, V[i].y); Vzw[i] = pack2(V[i].z, V[i].w);
            }
            #pragma unroll
            for (int i = 0; i < 4; i++)
                #pragma unroll
                for (int j = 0; j < 4; j++) {
                    fma2(a2[i * 4 + j], Kxy[i], Vxy[j]);
                    fma2(a2[i * 4 + j], Kzw[i], Vzw[j]);
                }
        }
        float* po = g_partial + ((size_t)tile * NCHUNK + chunk) * NPART;
        #pragma unroll
        for (int i = 0; i < 4; i++)
            #pragma unroll
            for (int j = 0; j < 4; j++) {
                float2 v = unpack2(a2[i * 4 + j]);
                po[h * 144 + (db * 4 + i) * 12 + eb * 4 + j] = v.x + v.y;
            }
    } else if (tid < 768) {
        int s = tid - 576;
        int chunk = s & 7, ci = s >> 3;              // ci 0..23
        float a[4] = {0.f, 0.f, 0.f, 0.f};
        #pragma unroll
        for (int t = 0; t < 4; t++)
            #pragma unroll
            for (int i = 0; i < 4; i++) {
                float4 K = ((const float4*)(sK + (ci * 4 + i) * RS))[chunk * 4 + t];
                a[i] += K.x + K.y + K.z + K.w;
            }
        float* po = g_partial + ((size_t)tile * NCHUNK + chunk) * NPART;
        #pragma unroll
        for (int i = 0; i < 4; i++) po[1152 + ci * 4 + i] = a[i];
    }
}

// ===== stage-1 reduce: 32 segments of 256 chunk-rows per batch =====
__global__ void red1_kernel()
{
    int idx = blockIdx.x * 256 + threadIdx.x;
    int b = blockIdx.y, seg = blockIdx.z;
    if (idx >= NPART) return;
    float a = 0.f;
    const float* p = g_partial +
        ((size_t)b * NTILE * NCHUNK + (size_t)seg * (NTILE * NCHUNK / NSEG)) * NPART + idx;
    #pragma unroll 8
    for (int t = 0; t < NTILE * NCHUNK / NSEG; t++) a += p[(size_t)t * NPART];
    g_red1[(seg * BB + b) * NPART + idx] = a;
}

// ===== stage-2 reduce (fixed order) =====
__global__ void red2_kernel()
{
    int gid = blockIdx.x * 256 + threadIdx.x;
    if (gid >= BB * NPART) return;
    int b = gid / NPART, idx = gid - b * NPART;
    float a = 0.f;
    #pragma unroll
    for (int s = 0; s < NSEG; s++) a += g_red1[(s * BB + b) * NPART + idx];
    g_red[gid] = a;
}

// ===== WC^T[b][c'][o] = (sum_e Wproj[o,h12+e] * KV[b,h,d,e]) / sumK[b,c'] =====
__global__ void ctx2_kernel(const float* __restrict__ Wproj)
{
    int gid = blockIdx.x * 256 + threadIdx.x;
    if (gid >= BB * 9216) return;
    int b = gid / 9216;
    int r = gid - b * 9216;
    int o = r / 96, cp = r - o * 96;       // cp = h*12+d
    int h = cp / 12;
    const float* kv = g_red + b * NPART + h * 144 + (cp - h * 12) * 12;
    const float* wp = Wproj + o * 96 + h * 12;
    float a = 0.f;
    #pragma unroll
    for (int e = 0; e < 12; e++) a += wp[e] * kv[e];
    g_WCt[(b * 96 + cp) * 96 + o] = a / g_red[b * NPART + 1152 + cp];
}

// =====================================================================
// Kernel C (R8 shape + WC-fold): stage x + Wq smem -> q GEMM ->
// (reload sW with WCt) softmax -> p in-place -> WC GEMM -> out.
// 256 thr, 4 tok x 12 ch, 2 CTAs/SM.
// =====================================================================
__global__ void __launch_bounds__(256, 2)
out2_kernel(const float* __restrict__ x, const float* __restrict__ Wq,
            float* __restrict__ out)
{
    extern __shared__ float sm[];
    float* sX = sm;                 // [96][RS]: x, then p in-place
    float* sW = sX + 96 * RS;       // [96][WS]: Wq, then WCt

    const int tile = blockIdx.x;
    const int b    = tile >> 10;
    const int n0   = (tile & (NTILE - 1)) * TN;
    const int tid  = threadIdx.x;
    const int tg   = tid & 31;
    const int og   = tid >> 5;
    const int nt   = tg * 4;

    const float* xb = x + (size_t)b * CCH * NTOK + n0;
    for (int i = tid; i < CCH * (TN / 4); i += 256) {
        int c = i >> 5, n4 = i & 31;
        ((float4*)(sX + c * RS))[n4] = ((const float4*)(xb + (size_t)c * NTOK))[n4];
    }
    for (int i = tid; i < CCH * CCH; i += 256) {
        int o = i / 96, c = i - o * 96;
        sW[c * WS + o] = Wq[i];
    }
    __syncthreads();

    // q GEMM: 24 accs (4 tok x 12 ch)
    ull aq[24];
    #pragma unroll
    for (int j = 0; j < 24; j++) aq[j] = 0ull;
    #pragma unroll 2
    for (int c = 0; c < 96; c++) {
        float4 xv = *(const float4*)(sX + c * RS + nt);
        ull x0 = pack2(xv.x, xv.x), x1 = pack2(xv.y, xv.y);
        ull x2 = pack2(xv.z, xv.z), x3 = pack2(xv.w, xv.w);
        const ulonglong2* w4 = (const ulonglong2*)(sW + c * WS + og * 12);
        #pragma unroll
        for (int jj = 0; jj < 3; jj++) {
            ulonglong2 w = w4[jj];
            fma2(aq[jj * 8 + 0], w.x, x0); fma2(aq[jj * 8 + 1], w.x, x1);
            fma2(aq[jj * 8 + 2], w.x, x2); fma2(aq[jj * 8 + 3], w.x, x3);
            fma2(aq[jj * 8 + 4], w.y, x0); fma2(aq[jj * 8 + 5], w.y, x1);
            fma2(aq[jj * 8 + 6], w.y, x2); fma2(aq[jj * 8 + 7], w.y, x3);
        }
    }
    __syncthreads();    // all reads of x (sX) and Wq (sW) complete

    // reload sW with WCt while softmax proceeds
    const float* wct = g_WCt + b * 9216;
    for (int i = tid; i < CCH * CCH; i += 256) {
        int cp = i / 96, o = i - cp * 96;       // wct is [c'][o] already
        sW[cp * WS + o] = wct[i];
    }

    // softmax over head dim per token; write p into sX in-place
    #pragma unroll
    for (int t = 0; t < 4; t++) {
        float qv[12];
        #pragma unroll
        for (int jj = 0; jj < 3; jj++)
            #pragma unroll
            for (int s = 0; s < 2; s++) {
                float2 v = unpack2(aq[jj * 8 + s * 4 + t]);
                qv[jj * 4 + s * 2]     = v.x;
                qv[jj * 4 + s * 2 + 1] = v.y;
            }
        float m = qv[0];
        #pragma unroll
        for (int i = 1; i < 12; i++) m = fmaxf(m, qv[i]);
        float p[12]; float sum = 0.f;
        #pragma unroll
        for (int i = 0; i < 12; i++) { p[i] = __expf(qv[i] - m); sum += p[i]; }
        float inv = 1.f / sum;
        #pragma unroll
        for (int i = 0; i < 12; i++)
            sX[(og * 12 + i) * RS + nt + t] = p[i] * inv;
    }
    __syncthreads();    // p tile + WCt load complete

    // WC GEMM: out[o][n] = sum_c' WC[o][c'] * p[c'][n]
    ull ap[24];
    #pragma unroll
    for (int j = 0; j < 24; j++) ap[j] = 0ull;
    #pragma unroll 2
    for (int c = 0; c < 96; c++) {
        float4 pv = *(const float4*)(sX + c * RS + nt);
        ull x0 = pack2(pv.x, pv.x), x1 = pack2(pv.y, pv.y);
        ull x2 = pack2(pv.z, pv.z), x3 = pack2(pv.w, pv.w);
        const ulonglong2* w4 = (const ulonglong2*)(sW + c * WS + og * 12);
        #pragma unroll
        for (int jj = 0; jj < 3; jj++) {
            ulonglong2 w = w4[jj];
            fma2(ap[jj * 8 + 0], w.x, x0); fma2(ap[jj * 8 + 1], w.x, x1);
            fma2(ap[jj * 8 + 2], w.x, x2); fma2(ap[jj * 8 + 3], w.x, x3);
            fma2(ap[jj * 8 + 4], w.y, x0); fma2(ap[jj * 8 + 5], w.y, x1);
            fma2(ap[jj * 8 + 6], w.y, x2); fma2(ap[jj * 8 + 7], w.y, x3);
        }
    }

    float* ob = out + (size_t)b * CCH * NTOK + n0 + nt;
    #pragma unroll
    for (int jj = 0; jj < 3; jj++)
        #pragma unroll
        for (int s = 0; s < 2; s++) {
            float2 v0 = unpack2(ap[jj * 8 + s * 4 + 0]);
            float2 v1 = unpack2(ap[jj * 8 + s * 4 + 1]);
            float2 v2 = unpack2(ap[jj * 8 + s * 4 + 2]);
            float2 v3 = unpack2(ap[jj * 8 + s * 4 + 3]);
            int o = og * 12 + jj * 4 + s * 2;
            *(float4*)(ob + (size_t)o * NTOK)       = make_float4(v0.x, v1.x, v2.x, v3.x);
            *(float4*)(ob + (size_t)(o + 1) * NTOK) = make_float4(v0.y, v1.y, v2.y, v3.y);
        }
}

extern "C" void kernel_launch(void* const* d_in, const int* in_sizes, int n_in,
                              void* d_out, int out_size)
{
    const float* x  = (const float*)d_in[0];
    const float* Wq = (const float*)d_in[1];
    const float* Wk = (const float*)d_in[2];
    const float* Wv = (const float*)d_in[3];
    const float* Wp = (const float*)d_in[4];
    float* out = (float*)d_out;

    const size_t smA = (size_t)(3 * 96 * RS + 2 * 96 * WS) * sizeof(float);   // 228,864 B
    const size_t smC = (size_t)(96 * RS + 96 * WS) * sizeof(float);           //  89,088 B
    cudaFuncSetAttribute(kv_kernel,   cudaFuncAttributeMaxDynamicSharedMemorySize, (int)smA);
    cudaFuncSetAttribute(out2_kernel, cudaFuncAttributeMaxDynamicSharedMemorySize, (int)smC);

    kv_kernel<<<NBLK, 1024, smA>>>(x, Wk, Wv);
    red1_kernel<<<dim3(5, BB, NSEG), 256>>>();
    red2_kernel<<<(BB * NPART + 255) / 256, 256>>>();
    ctx2_kernel<<<(BB * 9216 + 255) / 256, 256>>>(Wp);
    out2_kernel<<<NBLK, 256, smC>>>(x, Wq, out);
}